// round 16
// baseline (speedup 1.0000x reference)
#include <cuda_runtime.h>

#define NVOC   64
#define SD     32
#define FD     16
#define NB     256
#define SEQL   2048
#define NSTEP  2047               /* delta steps, t = 0..2046 */
#define FSPLIT 960                /* forward covers t in [0, FSPLIT), mult of 64 */
#define NFWD   128                /* forward blocks, 2 batches each */
#define NBWD   16                 /* backward blocks, 16 batches each */
#define BPB    16                 /* batches per backward block */
#define NCHUNK ((NSTEP - FSPLIT + 63) / 64)

// LUT: per vocab id, 64 floats = [k_sem(32) | k_fast(16) | k_slow(16)]
__device__ float g_lut[NVOC * 64];
// inv(k.k + 1e-6): [0..63]=sem, [64..127]=fast, [128..191]=slow
__device__ float g_inv[3 * NVOC];
// forward-half state matrices
__device__ float g_Ms [NB * SD * SD];
__device__ float g_Mef[NB * FD * FD];
__device__ float g_Mes[NB * FD * FD];
// backward-half results: u at split, c_tail (packed [sem|fast|slow])
__device__ float g_u [NB * 64];
__device__ float g_ct[NB * 64];

// ---------------------------------------------------------------------------
// Kernel 1: per-token-id LUT. Heavy phases split-K across all 128 threads.
// ---------------------------------------------------------------------------
__global__ void lut_kernel(const float* __restrict__ embed,
                           const float* __restrict__ w1, const float* __restrict__ b1,
                           const float* __restrict__ w2, const float* __restrict__ b2,
                           const float* __restrict__ ln_g, const float* __restrict__ ln_b,
                           const float* __restrict__ sem_w, const float* __restrict__ sem_b,
                           const float* __restrict__ fast_w, const float* __restrict__ fast_b,
                           const float* __restrict__ slow_w, const float* __restrict__ slow_b)
{
    const int v = blockIdx.x;
    const int j = threadIdx.x;   // 0..127

    __shared__ float e[64];
    __shared__ float h1[128];
    __shared__ float part[128];
    __shared__ float x[64];
    __shared__ float xn[64];
    __shared__ float part2[128];
    __shared__ float kk[64];

    if (j < 64) e[j] = embed[v * 64 + j];
    __syncthreads();

    // FFN1: h1[j] = relu(e . w1[:,j] + b1[j])  (all 128 threads)
    {
        float a[8] = {0,0,0,0,0,0,0,0};
        #pragma unroll
        for (int d0 = 0; d0 < 64; d0 += 8)
            #pragma unroll
            for (int q = 0; q < 8; q++)
                a[q] = fmaf(e[d0 + q], w1[(d0 + q) * 128 + j], a[q]);
        float acc = ((a[0]+a[1])+(a[2]+a[3])) + ((a[4]+a[5])+(a[6]+a[7])) + b1[j];
        h1[j] = fmaxf(acc, 0.0f);
    }
    __syncthreads();

    // FFN2 split-K: thread (g, jj) covers d in [g*64, g*64+64) for output jj
    {
        const int jj = j & 63;
        const int g  = j >> 6;
        const int dbase = g * 64;
        float a[8] = {0,0,0,0,0,0,0,0};
        #pragma unroll
        for (int d0 = 0; d0 < 64; d0 += 8)
            #pragma unroll
            for (int q = 0; q < 8; q++)
                a[q] = fmaf(h1[dbase + d0 + q], w2[(dbase + d0 + q) * 64 + jj], a[q]);
        part[j] = ((a[0]+a[1])+(a[2]+a[3])) + ((a[4]+a[5])+(a[6]+a[7]));
    }
    __syncthreads();
    if (j < 64) x[j] = e[j] + part[j] + part[j + 64] + b2[j];
    __syncthreads();

    // LayerNorm (redundant per-thread stats over 64 values)
    if (j < 64) {
        float mu = 0.0f;
        #pragma unroll
        for (int d = 0; d < 64; d++) mu += x[d];
        mu *= (1.0f / 64.0f);
        float var = 0.0f;
        #pragma unroll
        for (int d = 0; d < 64; d++) { float dd = x[d] - mu; var = fmaf(dd, dd, var); }
        var *= (1.0f / 64.0f);
        float r = rsqrtf(var + 1e-5f);
        xn[j] = (x[j] - mu) * r * ln_g[j] + ln_b[j];
    }
    __syncthreads();

    // Projections split-K: thread (g, jj) covers d in [g*32, g*32+32)
    {
        const int jj = j & 63;
        const int g  = j >> 6;
        const int dbase = g * 32;
        const float* wp; int cols, cc;
        if (jj < 32)      { wp = sem_w;  cols = SD; cc = jj; }
        else if (jj < 48) { wp = fast_w; cols = FD; cc = jj - 32; }
        else              { wp = slow_w; cols = FD; cc = jj - 48; }
        float a[8] = {0,0,0,0,0,0,0,0};
        #pragma unroll
        for (int d0 = 0; d0 < 32; d0 += 8)
            #pragma unroll
            for (int q = 0; q < 8; q++)
                a[q] = fmaf(xn[dbase + d0 + q], wp[(dbase + d0 + q) * cols + cc], a[q]);
        part2[j] = ((a[0]+a[1])+(a[2]+a[3])) + ((a[4]+a[5])+(a[6]+a[7]));
    }
    __syncthreads();
    if (j < 64) {
        float bias;
        if (j < 32)      bias = sem_b[j];
        else if (j < 48) bias = fast_b[j - 32];
        else             bias = slow_b[j - 48];
        const float s = part2[j] + part2[j + 64] + bias;
        kk[j] = s;
        g_lut[v * 64 + j] = s;
    }
    __syncthreads();

    if (j < 3) {
        const int lo = (j == 0) ? 0 : (j == 1) ? 32 : 48;
        const int hi = (j == 0) ? 32 : (j == 1) ? 48 : 64;
        float s = 0.0f;
        for (int d = lo; d < hi; d++) s = fmaf(kk[d], kk[d], s);
        g_inv[j * NVOC + v] = 1.0f / (s + 1e-6f);
    }
}

// ------------------------ forward helpers (scalar) -------------------------
__device__ __forceinline__ void fw_load32(const float* __restrict__ s_lut,
                                          const float* __restrict__ s_inv,
                                          int tok, int lane,
                                          float* __restrict__ k, float& ki, float& ikk)
{
    const float4* kp = reinterpret_cast<const float4*>(&s_lut[tok * 64]);
    #pragma unroll
    for (int q = 0; q < 8; q++) {
        float4 v = kp[q];
        k[4*q] = v.x; k[4*q+1] = v.y; k[4*q+2] = v.z; k[4*q+3] = v.w;
    }
    ki  = s_lut[tok * 64 + lane];
    ikk = s_inv[tok];
}

__device__ __forceinline__ void fw_step32(float* __restrict__ m,
                                          const float* __restrict__ k,
                                          float ki, float ikk)
{
    float a0 = 0.f, a1 = 0.f, a2 = 0.f, a3 = 0.f;
    #pragma unroll
    for (int j = 0; j < SD; j += 4) {
        a0 = fmaf(m[j+0], k[j+0], a0);
        a1 = fmaf(m[j+1], k[j+1], a1);
        a2 = fmaf(m[j+2], k[j+2], a2);
        a3 = fmaf(m[j+3], k[j+3], a3);
    }
    const float vp = (a0 + a1) + (a2 + a3);
    const float dv = fmaf(-vp, ikk, ki);
    #pragma unroll
    for (int j = 0; j < SD; j++) m[j] = fmaf(dv, k[j], m[j]);
}

__device__ __forceinline__ void fw_load16(const float* __restrict__ s_lut,
                                          const float* __restrict__ invp,
                                          int tok, int off, int r,
                                          float* __restrict__ k, float& kr, float& ikk)
{
    const float4* kp = reinterpret_cast<const float4*>(&s_lut[tok * 64 + off]);
    #pragma unroll
    for (int q = 0; q < 4; q++) {
        float4 v = kp[q];
        k[4*q] = v.x; k[4*q+1] = v.y; k[4*q+2] = v.z; k[4*q+3] = v.w;
    }
    kr  = s_lut[tok * 64 + off + r];
    ikk = invp[tok];
}

__device__ __forceinline__ void fw_step16(float* __restrict__ m,
                                          const float* __restrict__ k,
                                          float kr, float ikk, float wt)
{
    float a0 = 0.f, a1 = 0.f, a2 = 0.f, a3 = 0.f;
    #pragma unroll
    for (int j = 0; j < FD; j += 4) {
        a0 = fmaf(m[j+0], k[j+0], a0);
        a1 = fmaf(m[j+1], k[j+1], a1);
        a2 = fmaf(m[j+2], k[j+2], a2);
        a3 = fmaf(m[j+3], k[j+3], a3);
    }
    const float vp  = (a0 + a1) + (a2 + a3);
    const float dv  = fmaf(-vp, ikk, kr);
    const float wdv = wt * dv;
    #pragma unroll
    for (int j = 0; j < FD; j++) m[j] = fmaf(wdv, k[j], m[j]);
}

// -------------------- backward helpers (2 lanes per batch) -----------------
template<int HD>
__device__ __forceinline__ void bw_load(const float* __restrict__ lut,
                                        const float* __restrict__ inv, int scale_off,
                                        int tok, int koff,
                                        float* __restrict__ k, float& ikk)
{
    const float4* kb = reinterpret_cast<const float4*>(&lut[tok * 68 + koff]);
    #pragma unroll
    for (int q = 0; q < HD / 4; q++) {
        float4 v = kb[q];
        k[4*q] = v.x; k[4*q+1] = v.y; k[4*q+2] = v.z; k[4*q+3] = v.w;
    }
    ikk = inv[scale_off + tok];
}

template<int HD, int SCALE>
__device__ __forceinline__ void bw_step(float* __restrict__ u, float* __restrict__ c,
                                        float* __restrict__ pacc_row,
                                        const float* __restrict__ k, float ikk,
                                        int tok, int tt)
{
    const float invL = 1.0f / 2048.0f;
    float a0 = 0.f, a1 = 0.f, a2 = 0.f, a3 = 0.f;
    #pragma unroll
    for (int i = 0; i < HD; i += 4) {
        a0 = fmaf(k[i+0], u[i+0], a0);
        a1 = fmaf(k[i+1], u[i+1], a1);
        a2 = fmaf(k[i+2], u[i+2], a2);
        a3 = fmaf(k[i+3], u[i+3], a3);
    }
    const float part = (a0 + a1) + (a2 + a3);
    const float d = part + __shfl_xor_sync(0xffffffffu, part, 1);

    float p;
    if (SCALE == 0)       p = d;
    else if (SCALE == 1)  p = d * ((float)(tt + 1) * invL);
    else                  p = d * sqrtf((float)(tt + 1) * invL);

    if (SCALE == 0) {
        pacc_row[tok] += p;
    } else {
        #pragma unroll
        for (int i = 0; i < HD; i++) c[i] = fmaf(p, k[i], c[i]);
    }
    const float q = p * ikk;
    #pragma unroll
    for (int i = 0; i < HD; i++) u[i] = fmaf(-q, k[i], u[i]);
}

template<int HD, int SCALE>
__device__ __forceinline__ void bw_chunk(float* __restrict__ u, float* __restrict__ c,
                                         float* __restrict__ pacc_row,
                                         int t_hi, int t_lo, int koff,
                                         const float* __restrict__ lut,
                                         const float* __restrict__ inv,
                                         const int* __restrict__ tokrow)
{
    const int soff = SCALE * 64;

    int i = t_hi - t_lo;
    int toka = tokrow[i];
    float ka[HD], ikka;
    bw_load<HD>(lut, inv, soff, toka, koff, ka, ikka);

    if (((i + 1) & 1) != 0) {                 // odd count: peel one step
        bw_step<HD, SCALE>(u, c, pacc_row, ka, ikka, toka, t_lo + i);
        i--;
        if (i < 0) return;
        toka = tokrow[i];
        bw_load<HD>(lut, inv, soff, toka, koff, ka, ikka);
    }

    #pragma unroll 4
    for (; i >= 1; i -= 2) {
        const int tokb = tokrow[i - 1];
        float kb[HD], ikkb;
        bw_load<HD>(lut, inv, soff, tokb, koff, kb, ikkb);
        bw_step<HD, SCALE>(u, c, pacc_row, ka, ikka, toka, t_lo + i);

        const int na = (i >= 3) ? (i - 2) : 0;
        toka = tokrow[na];
        bw_load<HD>(lut, inv, soff, toka, koff, ka, ikka);
        bw_step<HD, SCALE>(u, c, pacc_row, kb, ikkb, tokb, t_lo + i - 1);
    }
}

// ---------------------------------------------------------------------------
// Kernel 2: one wave of 144 blocks
//   blocks 0..127  : forward matrix scan, 2 batches/block
//   blocks 128..143: backward adjoint, 16 batches/block, 2 lanes per batch
// ---------------------------------------------------------------------------
__global__ void __launch_bounds__(128)
scan_kernel(const int* __restrict__ seq)
{
    __shared__ __align__(16) char raw[36864];
    const int tid  = threadIdx.x;
    const int w    = tid >> 5;
    const int lane = tid & 31;

    if (blockIdx.x < NFWD) {
        // ========================= FORWARD =========================
        float* s_lut = (float*)raw;                    // 16384 B
        float* s_inv = (float*)(raw + 16384);          // 768 B
        int*   s_seq = (int*)  (raw + 17152);          // 2*(FSPLIT+8) ints

        const int b0 = blockIdx.x * 2;
        for (int i = tid; i < NVOC * 64; i += 128) s_lut[i] = g_lut[i];
        for (int i = tid; i < 3 * NVOC;  i += 128) s_inv[i] = g_inv[i];
        for (int i = tid; i < FSPLIT; i += 128) {
            s_seq[i]              = seq[ b0      * SEQL + i];
            s_seq[FSPLIT + 8 + i] = seq[(b0 + 1) * SEQL + i];
        }
        if (tid < 8) {
            s_seq[FSPLIT + tid]         = 0;
            s_seq[2 * FSPLIT + 8 + tid] = 0;
        }
        __syncthreads();

        const int  bsel = w >> 1;
        const int  b    = b0 + bsel;
        const int* sq   = s_seq + bsel * (FSPLIT + 8);

        if ((w & 1) == 0) {
            // ---- Ms 32x32, lane = row, manual 2-step double buffer ----
            float m[SD];
            #pragma unroll
            for (int j = 0; j < SD; j++) m[j] = 0.0f;

            float ka[SD], kb[SD], kia, ikka, kib, ikkb;
            fw_load32(s_lut, s_inv, sq[0], lane, ka, kia, ikka);

            #pragma unroll 4
            for (int t = 0; t < FSPLIT; t += 2) {
                fw_load32(s_lut, s_inv, sq[t + 1], lane, kb, kib, ikkb);
                fw_step32(m, ka, kia, ikka);
                fw_load32(s_lut, s_inv, sq[t + 2], lane, ka, kia, ikka);
                fw_step32(m, kb, kib, ikkb);
            }

            float4* dst = reinterpret_cast<float4*>(&g_Ms[(b * SD + lane) * SD]);
            #pragma unroll
            for (int q = 0; q < 8; q++)
                dst[q] = make_float4(m[4*q], m[4*q+1], m[4*q+2], m[4*q+3]);
        } else {
            // ---- Mef (lanes 0-15) / Mes (lanes 16-31), lane%16 = row ----
            const bool isf = (lane < 16);
            const int  r   = lane & 15;
            const int  off = isf ? 32 : 48;
            const float* invp = s_inv + (isf ? 64 : 128);
            const float invL = 1.0f / 2048.0f;

            float m[FD];
            #pragma unroll
            for (int j = 0; j < FD; j++) m[j] = 0.0f;

            float ka[FD], kb[FD], kra, ikka, krb, ikkb;
            fw_load16(s_lut, invp, sq[0], off, r, ka, kra, ikka);

            #pragma unroll 4
            for (int t = 0; t < FSPLIT; t += 2) {
                float wa = (float)(t + 1) * invL;
                float wb = (float)(t + 2) * invL;
                if (!isf) { wa = sqrtf(wa); wb = sqrtf(wb); }

                fw_load16(s_lut, invp, sq[t + 1], off, r, kb, krb, ikkb);
                fw_step16(m, ka, kra, ikka, wa);
                fw_load16(s_lut, invp, sq[t + 2], off, r, ka, kra, ikka);
                fw_step16(m, kb, krb, ikkb, wb);
            }

            float* basep = isf ? g_Mef : g_Mes;
            float4* dst = reinterpret_cast<float4*>(&basep[(b * FD + r) * FD]);
            #pragma unroll
            for (int q = 0; q < 4; q++)
                dst[q] = make_float4(m[4*q], m[4*q+1], m[4*q+2], m[4*q+3]);
        }
    } else {
        // ========================= BACKWARD =========================
        float* s_lutP = (float*)raw;                    // 64*68*4 = 17408
        float* s_invB = (float*)(raw + 17408);          // 768
        int*   s_tok  = (int*)  (raw + 18176);          // 2*16*68 ints = 8704
        float* s_pacc = (float*)(raw + 26880);          // 32*65*4 = 8320

        const int bb = blockIdx.x - NFWD;               // 0..15
        const int b0 = bb * BPB;
        const int bi = lane >> 1;                       // batch index in block
        const int b  = b0 + bi;
        const int half = lane & 1;

        for (int i = tid; i < NVOC * 64; i += 128) {
            const int rr = i >> 6, cc = i & 63;
            s_lutP[rr * 68 + cc] = g_lut[i];
        }
        for (int i = tid; i < 3 * NVOC; i += 128) s_invB[i] = g_inv[i];
        for (int i = tid; i < 32 * 65; i += 128) s_pacc[i] = 0.0f;

        // stage top chunk: [buf][BPB batches][68] ints, 64 tokens each
        {
            const int base = FSPLIT + 64 * (NCHUNK - 1);
            const int buf  = (NCHUNK - 1) & 1;
            for (int i = tid; i < BPB * 16; i += 128) {
                const int bbx = i >> 4, q = i & 15;
                *reinterpret_cast<int4*>(&s_tok[(buf * BPB + bbx) * 68 + q * 4]) =
                    *reinterpret_cast<const int4*>(&seq[(b0 + bbx) * SEQL + base + q * 4]);
            }
        }
        __syncthreads();

        // per-warp scale config
        const int off  = (w == 0) ? 0 : (w == 1) ? 32 : 48;
        const int HDw  = (w == 0) ? 16 : 8;             // half-dim
        const int koff = off + half * HDw;

        float u[16], c[16];
        if (w < 3) {
            const int tokq = __ldg(&seq[b * SEQL + SEQL - 1]);
            for (int i = 0; i < HDw; i++) {
                u[i] = s_lutP[tokq * 68 + koff + i];
                c[i] = 0.0f;
            }
        }

        float* pacc_row = &s_pacc[lane * 65];

        for (int ci = NCHUNK - 1; ci >= 0; ci--) {
            const int c_lo = FSPLIT + 64 * ci;
            const int t_hi = (c_lo + 63 < NSTEP - 1) ? (c_lo + 63) : (NSTEP - 1);
            const int buf  = ci & 1;
            const int* tokrow = &s_tok[(buf * BPB + bi) * 68];

            if (w == 3) {
                if (ci > 0) {
                    const int nbase = FSPLIT + 64 * (ci - 1);
                    const int nbuf  = (ci - 1) & 1;
                    for (int i = lane; i < BPB * 16; i += 32) {
                        const int bbx = i >> 4, q = i & 15;
                        *reinterpret_cast<int4*>(&s_tok[(nbuf * BPB + bbx) * 68 + q * 4]) =
                            *reinterpret_cast<const int4*>(&seq[(b0 + bbx) * SEQL + nbase + q * 4]);
                    }
                }
            } else if (w == 0) {
                bw_chunk<16, 0>(u, c, pacc_row, t_hi, c_lo, koff, s_lutP, s_invB, tokrow);
            } else if (w == 1) {
                bw_chunk<8, 1>(u, c, pacc_row, t_hi, c_lo, koff, s_lutP, s_invB, tokrow);
            } else {
                bw_chunk<8, 2>(u, c, pacc_row, t_hi, c_lo, koff, s_lutP, s_invB, tokrow);
            }
            __syncthreads();
        }

        // sem: reconstruct own half of c from vocab buckets: c += pacc[v] * k_v[half]
        if (w == 0) {
            #pragma unroll 2
            for (int v = 0; v < NVOC; v++) {
                const float pv = pacc_row[v];
                const float4* kp = reinterpret_cast<const float4*>(&s_lutP[v * 68 + half * 16]);
                #pragma unroll
                for (int q = 0; q < 4; q++) {
                    float4 kv = kp[q];
                    c[4*q+0] = fmaf(pv, kv.x, c[4*q+0]);
                    c[4*q+1] = fmaf(pv, kv.y, c[4*q+1]);
                    c[4*q+2] = fmaf(pv, kv.z, c[4*q+2]);
                    c[4*q+3] = fmaf(pv, kv.w, c[4*q+3]);
                }
            }
        }

        if (w < 3) {
            float4* up = reinterpret_cast<float4*>(&g_u [b * 64 + koff]);
            float4* cp = reinterpret_cast<float4*>(&g_ct[b * 64 + koff]);
            for (int q = 0; q < HDw / 4; q++) {
                up[q] = make_float4(u[4*q], u[4*q+1], u[4*q+2], u[4*q+3]);
                cp[q] = make_float4(c[4*q], c[4*q+1], c[4*q+2], c[4*q+3]);
            }
        }
    }
}

// ---------------------------------------------------------------------------
// Kernel 3: join  c = M_F u_F + c_tail , then readout GEMM.
// out_w staged in smem (bulk float4, one latency wave) -> GEMM from smem.
// ---------------------------------------------------------------------------
__global__ void __launch_bounds__(64)
join_kernel(const float* __restrict__ out_w, const float* __restrict__ out_b,
            float* __restrict__ out)
{
    __shared__ float sw[64 * 64];   // 16 KB staged out_w
    __shared__ float su[64];
    __shared__ float sc[64];
    const int b   = blockIdx.x;
    const int tid = threadIdx.x;

    {
        const float4* src = reinterpret_cast<const float4*>(out_w);
        float4* dst = reinterpret_cast<float4*>(sw);
        #pragma unroll
        for (int i = 0; i < 16; i++)
            dst[tid + 64 * i] = __ldg(&src[tid + 64 * i]);
    }
    su[tid] = __ldg(&g_u[b * 64 + tid]);
    __syncthreads();

    float acc = __ldg(&g_ct[b * 64 + tid]);
    if (tid < 32) {
        const float4* mp = reinterpret_cast<const float4*>(&g_Ms[(b * SD + tid) * SD]);
        float a0 = 0.f, a1 = 0.f, a2 = 0.f, a3 = 0.f;
        #pragma unroll
        for (int q = 0; q < 8; q++) {
            float4 mv = __ldg(&mp[q]);
            a0 = fmaf(mv.x, su[4*q+0], a0);
            a1 = fmaf(mv.y, su[4*q+1], a1);
            a2 = fmaf(mv.z, su[4*q+2], a2);
            a3 = fmaf(mv.w, su[4*q+3], a3);
        }
        acc += (a0 + a1) + (a2 + a3);
    } else if (tid < 48) {
        const int r = tid - 32;
        const float4* mp = reinterpret_cast<const float4*>(&g_Mef[(b * FD + r) * FD]);
        float a0 = 0.f, a1 = 0.f;
        #pragma unroll
        for (int q = 0; q < 4; q++) {
            float4 mv = __ldg(&mp[q]);
            a0 = fmaf(mv.x, su[32 + 4*q+0], a0);
            a1 = fmaf(mv.y, su[32 + 4*q+1], a1);
            a0 = fmaf(mv.z, su[32 + 4*q+2], a0);
            a1 = fmaf(mv.w, su[32 + 4*q+3], a1);
        }
        acc += a0 + a1;
    } else {
        const int r = tid - 48;
        const float4* mp = reinterpret_cast<const float4*>(&g_Mes[(b * FD + r) * FD]);
        float a0 = 0.f, a1 = 0.f;
        #pragma unroll
        for (int q = 0; q < 4; q++) {
            float4 mv = __ldg(&mp[q]);
            a0 = fmaf(mv.x, su[48 + 4*q+0], a0);
            a1 = fmaf(mv.y, su[48 + 4*q+1], a1);
            a0 = fmaf(mv.z, su[48 + 4*q+2], a0);
            a1 = fmaf(mv.w, su[48 + 4*q+3], a1);
        }
        acc += a0 + a1;
    }
    sc[tid] = acc;
    __syncthreads();

    float o0 = 0.f, o1 = 0.f, o2 = 0.f, o3 = 0.f;
    float o4 = 0.f, o5 = 0.f, o6 = 0.f, o7 = 0.f;
    #pragma unroll
    for (int d = 0; d < 64; d += 8) {
        o0 = fmaf(sc[d+0], sw[(d+0) * 64 + tid], o0);
        o1 = fmaf(sc[d+1], sw[(d+1) * 64 + tid], o1);
        o2 = fmaf(sc[d+2], sw[(d+2) * 64 + tid], o2);
        o3 = fmaf(sc[d+3], sw[(d+3) * 64 + tid], o3);
        o4 = fmaf(sc[d+4], sw[(d+4) * 64 + tid], o4);
        o5 = fmaf(sc[d+5], sw[(d+5) * 64 + tid], o5);
        o6 = fmaf(sc[d+6], sw[(d+6) * 64 + tid], o6);
        o7 = fmaf(sc[d+7], sw[(d+7) * 64 + tid], o7);
    }
    const float osum = ((o0 + o1) + (o2 + o3)) + ((o4 + o5) + (o6 + o7));
    out[b * 64 + tid] = osum + __ldg(&out_b[tid]);
}

// ---------------------------------------------------------------------------
extern "C" void kernel_launch(void* const* d_in, const int* in_sizes, int n_in,
                              void* d_out, int out_size)
{
    const int*   seq    = (const int*)  d_in[0];
    const float* embed  = (const float*)d_in[1];
    const float* w1     = (const float*)d_in[2];
    const float* b1     = (const float*)d_in[3];
    const float* w2     = (const float*)d_in[4];
    const float* b2     = (const float*)d_in[5];
    const float* ln_g   = (const float*)d_in[6];
    const float* ln_b   = (const float*)d_in[7];
    const float* sem_w  = (const float*)d_in[8];
    const float* sem_b  = (const float*)d_in[9];
    const float* fast_w = (const float*)d_in[10];
    const float* fast_b = (const float*)d_in[11];
    const float* slow_w = (const float*)d_in[12];
    const float* slow_b = (const float*)d_in[13];
    const float* out_w  = (const float*)d_in[14];
    const float* out_b  = (const float*)d_in[15];
    float* out = (float*)d_out;

    lut_kernel<<<NVOC, 128>>>(embed, w1, b1, w2, b2, ln_g, ln_b,
                              sem_w, sem_b, fast_w, fast_b, slow_w, slow_b);
    scan_kernel<<<NFWD + NBWD, 128>>>(seq);
    join_kernel<<<NB, 64>>>(out_w, out_b, out);
}

// round 17
// speedup vs baseline: 1.0708x; 1.0708x over previous
#include <cuda_runtime.h>

#define NVOC   64
#define SD     32
#define FD     16
#define NB     256
#define SEQL   2048
#define NSTEP  2047               /* delta steps, t = 0..2046 */
#define FSPLIT 960                /* forward covers t in [0, FSPLIT), mult of 64 */
#define NFWD   128                /* forward blocks, 2 batches each */
#define NBWD   16                 /* backward blocks, 16 batches each */
#define BPB    16                 /* batches per backward block */
#define NCHUNK ((NSTEP - FSPLIT + 63) / 64)

// LUT: per vocab id, 64 floats = [k_sem(32) | k_fast(16) | k_slow(16)]
__device__ float g_lut[NVOC * 64];
// inv(k.k + 1e-6): [0..63]=sem, [64..127]=fast, [128..191]=slow
__device__ float g_inv[3 * NVOC];
// forward-half state matrices
__device__ float g_Ms [NB * SD * SD];
__device__ float g_Mef[NB * FD * FD];
__device__ float g_Mes[NB * FD * FD];
// backward-half results: u at split, c_tail (packed [sem|fast|slow])
__device__ float g_u [NB * 64];
__device__ float g_ct[NB * 64];

// ---------------------------------------------------------------------------
// Kernel 1: per-token-id LUT. Heavy phases split-K across all 128 threads.
// (validated R16: 7.8us)
// ---------------------------------------------------------------------------
__global__ void lut_kernel(const float* __restrict__ embed,
                           const float* __restrict__ w1, const float* __restrict__ b1,
                           const float* __restrict__ w2, const float* __restrict__ b2,
                           const float* __restrict__ ln_g, const float* __restrict__ ln_b,
                           const float* __restrict__ sem_w, const float* __restrict__ sem_b,
                           const float* __restrict__ fast_w, const float* __restrict__ fast_b,
                           const float* __restrict__ slow_w, const float* __restrict__ slow_b)
{
    const int v = blockIdx.x;
    const int j = threadIdx.x;   // 0..127

    __shared__ float e[64];
    __shared__ float h1[128];
    __shared__ float part[128];
    __shared__ float x[64];
    __shared__ float xn[64];
    __shared__ float part2[128];
    __shared__ float kk[64];

    if (j < 64) e[j] = embed[v * 64 + j];
    __syncthreads();

    // FFN1: h1[j] = relu(e . w1[:,j] + b1[j])  (all 128 threads)
    {
        float a[8] = {0,0,0,0,0,0,0,0};
        #pragma unroll
        for (int d0 = 0; d0 < 64; d0 += 8)
            #pragma unroll
            for (int q = 0; q < 8; q++)
                a[q] = fmaf(e[d0 + q], w1[(d0 + q) * 128 + j], a[q]);
        float acc = ((a[0]+a[1])+(a[2]+a[3])) + ((a[4]+a[5])+(a[6]+a[7])) + b1[j];
        h1[j] = fmaxf(acc, 0.0f);
    }
    __syncthreads();

    // FFN2 split-K: thread (g, jj) covers d in [g*64, g*64+64) for output jj
    {
        const int jj = j & 63;
        const int g  = j >> 6;
        const int dbase = g * 64;
        float a[8] = {0,0,0,0,0,0,0,0};
        #pragma unroll
        for (int d0 = 0; d0 < 64; d0 += 8)
            #pragma unroll
            for (int q = 0; q < 8; q++)
                a[q] = fmaf(h1[dbase + d0 + q], w2[(dbase + d0 + q) * 64 + jj], a[q]);
        part[j] = ((a[0]+a[1])+(a[2]+a[3])) + ((a[4]+a[5])+(a[6]+a[7]));
    }
    __syncthreads();
    if (j < 64) x[j] = e[j] + part[j] + part[j + 64] + b2[j];
    __syncthreads();

    // LayerNorm (redundant per-thread stats over 64 values)
    if (j < 64) {
        float mu = 0.0f;
        #pragma unroll
        for (int d = 0; d < 64; d++) mu += x[d];
        mu *= (1.0f / 64.0f);
        float var = 0.0f;
        #pragma unroll
        for (int d = 0; d < 64; d++) { float dd = x[d] - mu; var = fmaf(dd, dd, var); }
        var *= (1.0f / 64.0f);
        float r = rsqrtf(var + 1e-5f);
        xn[j] = (x[j] - mu) * r * ln_g[j] + ln_b[j];
    }
    __syncthreads();

    // Projections split-K: thread (g, jj) covers d in [g*32, g*32+32)
    {
        const int jj = j & 63;
        const int g  = j >> 6;
        const int dbase = g * 32;
        const float* wp; int cols, cc;
        if (jj < 32)      { wp = sem_w;  cols = SD; cc = jj; }
        else if (jj < 48) { wp = fast_w; cols = FD; cc = jj - 32; }
        else              { wp = slow_w; cols = FD; cc = jj - 48; }
        float a[8] = {0,0,0,0,0,0,0,0};
        #pragma unroll
        for (int d0 = 0; d0 < 32; d0 += 8)
            #pragma unroll
            for (int q = 0; q < 8; q++)
                a[q] = fmaf(xn[dbase + d0 + q], wp[(dbase + d0 + q) * cols + cc], a[q]);
        part2[j] = ((a[0]+a[1])+(a[2]+a[3])) + ((a[4]+a[5])+(a[6]+a[7]));
    }
    __syncthreads();
    if (j < 64) {
        float bias;
        if (j < 32)      bias = sem_b[j];
        else if (j < 48) bias = fast_b[j - 32];
        else             bias = slow_b[j - 48];
        const float s = part2[j] + part2[j + 64] + bias;
        kk[j] = s;
        g_lut[v * 64 + j] = s;
    }
    __syncthreads();

    if (j < 3) {
        const int lo = (j == 0) ? 0 : (j == 1) ? 32 : 48;
        const int hi = (j == 0) ? 32 : (j == 1) ? 48 : 64;
        float s = 0.0f;
        for (int d = lo; d < hi; d++) s = fmaf(kk[d], kk[d], s);
        g_inv[j * NVOC + v] = 1.0f / (s + 1e-6f);
    }
}

// ------------------------ forward helpers (scalar) -------------------------
__device__ __forceinline__ void fw_load32(const float* __restrict__ s_lut,
                                          const float* __restrict__ s_inv,
                                          int tok, int lane,
                                          float* __restrict__ k, float& ki, float& ikk)
{
    const float4* kp = reinterpret_cast<const float4*>(&s_lut[tok * 64]);
    #pragma unroll
    for (int q = 0; q < 8; q++) {
        float4 v = kp[q];
        k[4*q] = v.x; k[4*q+1] = v.y; k[4*q+2] = v.z; k[4*q+3] = v.w;
    }
    ki  = s_lut[tok * 64 + lane];
    ikk = s_inv[tok];
}

__device__ __forceinline__ void fw_step32(float* __restrict__ m,
                                          const float* __restrict__ k,
                                          float ki, float ikk)
{
    float a0 = 0.f, a1 = 0.f, a2 = 0.f, a3 = 0.f;
    #pragma unroll
    for (int j = 0; j < SD; j += 4) {
        a0 = fmaf(m[j+0], k[j+0], a0);
        a1 = fmaf(m[j+1], k[j+1], a1);
        a2 = fmaf(m[j+2], k[j+2], a2);
        a3 = fmaf(m[j+3], k[j+3], a3);
    }
    const float vp = (a0 + a1) + (a2 + a3);
    const float dv = fmaf(-vp, ikk, ki);
    #pragma unroll
    for (int j = 0; j < SD; j++) m[j] = fmaf(dv, k[j], m[j]);
}

__device__ __forceinline__ void fw_load16(const float* __restrict__ s_lut,
                                          const float* __restrict__ invp,
                                          int tok, int off, int r,
                                          float* __restrict__ k, float& kr, float& ikk)
{
    const float4* kp = reinterpret_cast<const float4*>(&s_lut[tok * 64 + off]);
    #pragma unroll
    for (int q = 0; q < 4; q++) {
        float4 v = kp[q];
        k[4*q] = v.x; k[4*q+1] = v.y; k[4*q+2] = v.z; k[4*q+3] = v.w;
    }
    kr  = s_lut[tok * 64 + off + r];
    ikk = invp[tok];
}

__device__ __forceinline__ void fw_step16(float* __restrict__ m,
                                          const float* __restrict__ k,
                                          float kr, float ikk, float wt)
{
    float a0 = 0.f, a1 = 0.f, a2 = 0.f, a3 = 0.f;
    #pragma unroll
    for (int j = 0; j < FD; j += 4) {
        a0 = fmaf(m[j+0], k[j+0], a0);
        a1 = fmaf(m[j+1], k[j+1], a1);
        a2 = fmaf(m[j+2], k[j+2], a2);
        a3 = fmaf(m[j+3], k[j+3], a3);
    }
    const float vp  = (a0 + a1) + (a2 + a3);
    const float dv  = fmaf(-vp, ikk, kr);
    const float wdv = wt * dv;
    #pragma unroll
    for (int j = 0; j < FD; j++) m[j] = fmaf(wdv, k[j], m[j]);
}

// -------------------- backward helpers (2 lanes per batch) -----------------
template<int HD>
__device__ __forceinline__ void bw_load(const float* __restrict__ lut,
                                        const float* __restrict__ inv, int scale_off,
                                        int tok, int koff,
                                        float* __restrict__ k, float& ikk)
{
    const float4* kb = reinterpret_cast<const float4*>(&lut[tok * 68 + koff]);
    #pragma unroll
    for (int q = 0; q < HD / 4; q++) {
        float4 v = kb[q];
        k[4*q] = v.x; k[4*q+1] = v.y; k[4*q+2] = v.z; k[4*q+3] = v.w;
    }
    ikk = inv[scale_off + tok];
}

template<int HD, int SCALE>
__device__ __forceinline__ void bw_step(float* __restrict__ u, float* __restrict__ c,
                                        float* __restrict__ pacc_row,
                                        const float* __restrict__ k, float ikk,
                                        int tok, int tt)
{
    const float invL = 1.0f / 2048.0f;
    float a0 = 0.f, a1 = 0.f, a2 = 0.f, a3 = 0.f;
    #pragma unroll
    for (int i = 0; i < HD; i += 4) {
        a0 = fmaf(k[i+0], u[i+0], a0);
        a1 = fmaf(k[i+1], u[i+1], a1);
        a2 = fmaf(k[i+2], u[i+2], a2);
        a3 = fmaf(k[i+3], u[i+3], a3);
    }
    const float part = (a0 + a1) + (a2 + a3);
    const float d = part + __shfl_xor_sync(0xffffffffu, part, 1);

    float p;
    if (SCALE == 0)       p = d;
    else if (SCALE == 1)  p = d * ((float)(tt + 1) * invL);
    else                  p = d * sqrtf((float)(tt + 1) * invL);

    if (SCALE == 0) {
        pacc_row[tok] += p;
    } else {
        #pragma unroll
        for (int i = 0; i < HD; i++) c[i] = fmaf(p, k[i], c[i]);
    }
    const float q = p * ikk;
    #pragma unroll
    for (int i = 0; i < HD; i++) u[i] = fmaf(-q, k[i], u[i]);
}

template<int HD, int SCALE>
__device__ __forceinline__ void bw_chunk(float* __restrict__ u, float* __restrict__ c,
                                         float* __restrict__ pacc_row,
                                         int t_hi, int t_lo, int koff,
                                         const float* __restrict__ lut,
                                         const float* __restrict__ inv,
                                         const int* __restrict__ tokrow)
{
    const int soff = SCALE * 64;

    int i = t_hi - t_lo;
    int toka = tokrow[i];
    float ka[HD], ikka;
    bw_load<HD>(lut, inv, soff, toka, koff, ka, ikka);

    if (((i + 1) & 1) != 0) {                 // odd count: peel one step
        bw_step<HD, SCALE>(u, c, pacc_row, ka, ikka, toka, t_lo + i);
        i--;
        if (i < 0) return;
        toka = tokrow[i];
        bw_load<HD>(lut, inv, soff, toka, koff, ka, ikka);
    }

    #pragma unroll 2
    for (; i >= 1; i -= 2) {
        const int tokb = tokrow[i - 1];
        float kb[HD], ikkb;
        bw_load<HD>(lut, inv, soff, tokb, koff, kb, ikkb);
        bw_step<HD, SCALE>(u, c, pacc_row, ka, ikka, toka, t_lo + i);

        const int na = (i >= 3) ? (i - 2) : 0;
        toka = tokrow[na];
        bw_load<HD>(lut, inv, soff, toka, koff, ka, ikka);
        bw_step<HD, SCALE>(u, c, pacc_row, kb, ikkb, tokb, t_lo + i - 1);
    }
}

// ---------------------------------------------------------------------------
// Kernel 2: one wave of 144 blocks (validated R15: scan ~98us, unroll 2)
//   blocks 0..127  : forward matrix scan, 2 batches/block
//   blocks 128..143: backward adjoint, 16 batches/block, 2 lanes per batch
// ---------------------------------------------------------------------------
__global__ void __launch_bounds__(128)
scan_kernel(const int* __restrict__ seq)
{
    __shared__ __align__(16) char raw[36864];
    const int tid  = threadIdx.x;
    const int w    = tid >> 5;
    const int lane = tid & 31;

    if (blockIdx.x < NFWD) {
        // ========================= FORWARD =========================
        float* s_lut = (float*)raw;                    // 16384 B
        float* s_inv = (float*)(raw + 16384);          // 768 B
        int*   s_seq = (int*)  (raw + 17152);          // 2*(FSPLIT+4) ints

        const int b0 = blockIdx.x * 2;
        for (int i = tid; i < NVOC * 64; i += 128) s_lut[i] = g_lut[i];
        for (int i = tid; i < 3 * NVOC;  i += 128) s_inv[i] = g_inv[i];
        for (int i = tid; i < FSPLIT; i += 128) {
            s_seq[i]              = seq[ b0      * SEQL + i];
            s_seq[FSPLIT + 4 + i] = seq[(b0 + 1) * SEQL + i];
        }
        if (tid < 4) {
            s_seq[FSPLIT + tid]         = 0;
            s_seq[2 * FSPLIT + 4 + tid] = 0;
        }
        __syncthreads();

        const int  bsel = w >> 1;
        const int  b    = b0 + bsel;
        const int* sq   = s_seq + bsel * (FSPLIT + 4);

        if ((w & 1) == 0) {
            // ---- Ms 32x32, lane = row, manual 2-step double buffer ----
            float m[SD];
            #pragma unroll
            for (int j = 0; j < SD; j++) m[j] = 0.0f;

            float ka[SD], kb[SD], kia, ikka, kib, ikkb;
            fw_load32(s_lut, s_inv, sq[0], lane, ka, kia, ikka);

            #pragma unroll 2
            for (int t = 0; t < FSPLIT; t += 2) {
                fw_load32(s_lut, s_inv, sq[t + 1], lane, kb, kib, ikkb);
                fw_step32(m, ka, kia, ikka);
                fw_load32(s_lut, s_inv, sq[t + 2], lane, ka, kia, ikka);
                fw_step32(m, kb, kib, ikkb);
            }

            float4* dst = reinterpret_cast<float4*>(&g_Ms[(b * SD + lane) * SD]);
            #pragma unroll
            for (int q = 0; q < 8; q++)
                dst[q] = make_float4(m[4*q], m[4*q+1], m[4*q+2], m[4*q+3]);
        } else {
            // ---- Mef (lanes 0-15) / Mes (lanes 16-31), lane%16 = row ----
            const bool isf = (lane < 16);
            const int  r   = lane & 15;
            const int  off = isf ? 32 : 48;
            const float* invp = s_inv + (isf ? 64 : 128);
            const float invL = 1.0f / 2048.0f;

            float m[FD];
            #pragma unroll
            for (int j = 0; j < FD; j++) m[j] = 0.0f;

            float ka[FD], kb[FD], kra, ikka, krb, ikkb;
            fw_load16(s_lut, invp, sq[0], off, r, ka, kra, ikka);

            #pragma unroll 2
            for (int t = 0; t < FSPLIT; t += 2) {
                float wa = (float)(t + 1) * invL;
                float wb = (float)(t + 2) * invL;
                if (!isf) { wa = sqrtf(wa); wb = sqrtf(wb); }

                fw_load16(s_lut, invp, sq[t + 1], off, r, kb, krb, ikkb);
                fw_step16(m, ka, kra, ikka, wa);
                fw_load16(s_lut, invp, sq[t + 2], off, r, ka, kra, ikka);
                fw_step16(m, kb, krb, ikkb, wb);
            }

            float* basep = isf ? g_Mef : g_Mes;
            float4* dst = reinterpret_cast<float4*>(&basep[(b * FD + r) * FD]);
            #pragma unroll
            for (int q = 0; q < 4; q++)
                dst[q] = make_float4(m[4*q], m[4*q+1], m[4*q+2], m[4*q+3]);
        }
    } else {
        // ========================= BACKWARD =========================
        float* s_lutP = (float*)raw;                    // 64*68*4 = 17408
        float* s_invB = (float*)(raw + 17408);          // 768
        int*   s_tok  = (int*)  (raw + 18176);          // 2*16*68 ints = 8704
        float* s_pacc = (float*)(raw + 26880);          // 32*65*4 = 8320

        const int bb = blockIdx.x - NFWD;               // 0..15
        const int b0 = bb * BPB;
        const int bi = lane >> 1;                       // batch index in block
        const int b  = b0 + bi;
        const int half = lane & 1;

        for (int i = tid; i < NVOC * 64; i += 128) {
            const int rr = i >> 6, cc = i & 63;
            s_lutP[rr * 68 + cc] = g_lut[i];
        }
        for (int i = tid; i < 3 * NVOC; i += 128) s_invB[i] = g_inv[i];
        for (int i = tid; i < 32 * 65; i += 128) s_pacc[i] = 0.0f;

        // stage top chunk: [buf][BPB batches][68] ints, 64 tokens each
        {
            const int base = FSPLIT + 64 * (NCHUNK - 1);
            const int buf  = (NCHUNK - 1) & 1;
            for (int i = tid; i < BPB * 16; i += 128) {
                const int bbx = i >> 4, q = i & 15;
                *reinterpret_cast<int4*>(&s_tok[(buf * BPB + bbx) * 68 + q * 4]) =
                    *reinterpret_cast<const int4*>(&seq[(b0 + bbx) * SEQL + base + q * 4]);
            }
        }
        __syncthreads();

        // per-warp scale config
        const int off  = (w == 0) ? 0 : (w == 1) ? 32 : 48;
        const int HDw  = (w == 0) ? 16 : 8;             // half-dim
        const int koff = off + half * HDw;

        float u[16], c[16];
        if (w < 3) {
            const int tokq = __ldg(&seq[b * SEQL + SEQL - 1]);
            for (int i = 0; i < HDw; i++) {
                u[i] = s_lutP[tokq * 68 + koff + i];
                c[i] = 0.0f;
            }
        }

        float* pacc_row = &s_pacc[lane * 65];

        for (int ci = NCHUNK - 1; ci >= 0; ci--) {
            const int c_lo = FSPLIT + 64 * ci;
            const int t_hi = (c_lo + 63 < NSTEP - 1) ? (c_lo + 63) : (NSTEP - 1);
            const int buf  = ci & 1;
            const int* tokrow = &s_tok[(buf * BPB + bi) * 68];

            if (w == 3) {
                if (ci > 0) {
                    const int nbase = FSPLIT + 64 * (ci - 1);
                    const int nbuf  = (ci - 1) & 1;
                    for (int i = lane; i < BPB * 16; i += 32) {
                        const int bbx = i >> 4, q = i & 15;
                        *reinterpret_cast<int4*>(&s_tok[(nbuf * BPB + bbx) * 68 + q * 4]) =
                            *reinterpret_cast<const int4*>(&seq[(b0 + bbx) * SEQL + nbase + q * 4]);
                    }
                }
            } else if (w == 0) {
                bw_chunk<16, 0>(u, c, pacc_row, t_hi, c_lo, koff, s_lutP, s_invB, tokrow);
            } else if (w == 1) {
                bw_chunk<8, 1>(u, c, pacc_row, t_hi, c_lo, koff, s_lutP, s_invB, tokrow);
            } else {
                bw_chunk<8, 2>(u, c, pacc_row, t_hi, c_lo, koff, s_lutP, s_invB, tokrow);
            }
            __syncthreads();
        }

        // sem: reconstruct own half of c from vocab buckets: c += pacc[v] * k_v[half]
        if (w == 0) {
            #pragma unroll 2
            for (int v = 0; v < NVOC; v++) {
                const float pv = pacc_row[v];
                const float4* kp = reinterpret_cast<const float4*>(&s_lutP[v * 68 + half * 16]);
                #pragma unroll
                for (int q = 0; q < 4; q++) {
                    float4 kv = kp[q];
                    c[4*q+0] = fmaf(pv, kv.x, c[4*q+0]);
                    c[4*q+1] = fmaf(pv, kv.y, c[4*q+1]);
                    c[4*q+2] = fmaf(pv, kv.z, c[4*q+2]);
                    c[4*q+3] = fmaf(pv, kv.w, c[4*q+3]);
                }
            }
        }

        if (w < 3) {
            float4* up = reinterpret_cast<float4*>(&g_u [b * 64 + koff]);
            float4* cp = reinterpret_cast<float4*>(&g_ct[b * 64 + koff]);
            for (int q = 0; q < HDw / 4; q++) {
                up[q] = make_float4(u[4*q], u[4*q+1], u[4*q+2], u[4*q+3]);
                cp[q] = make_float4(c[4*q], c[4*q+1], c[4*q+2], c[4*q+3]);
            }
        }
    }
}

// ---------------------------------------------------------------------------
// Kernel 3: join  c = M_F u_F + c_tail , then readout GEMM.
// out_w staged in smem (bulk float4, one latency wave) -> GEMM from smem.
// ---------------------------------------------------------------------------
__global__ void __launch_bounds__(64)
join_kernel(const float* __restrict__ out_w, const float* __restrict__ out_b,
            float* __restrict__ out)
{
    __shared__ float sw[64 * 64];   // 16 KB staged out_w
    __shared__ float su[64];
    __shared__ float sc[64];
    const int b   = blockIdx.x;
    const int tid = threadIdx.x;

    {
        const float4* src = reinterpret_cast<const float4*>(out_w);
        float4* dst = reinterpret_cast<float4*>(sw);
        #pragma unroll
        for (int i = 0; i < 16; i++)
            dst[tid + 64 * i] = __ldg(&src[tid + 64 * i]);
    }
    su[tid] = __ldg(&g_u[b * 64 + tid]);
    __syncthreads();

    float acc = __ldg(&g_ct[b * 64 + tid]);
    if (tid < 32) {
        const float4* mp = reinterpret_cast<const float4*>(&g_Ms[(b * SD + tid) * SD]);
        float a0 = 0.f, a1 = 0.f, a2 = 0.f, a3 = 0.f;
        #pragma unroll
        for (int q = 0; q < 8; q++) {
            float4 mv = __ldg(&mp[q]);
            a0 = fmaf(mv.x, su[4*q+0], a0);
            a1 = fmaf(mv.y, su[4*q+1], a1);
            a2 = fmaf(mv.z, su[4*q+2], a2);
            a3 = fmaf(mv.w, su[4*q+3], a3);
        }
        acc += (a0 + a1) + (a2 + a3);
    } else if (tid < 48) {
        const int r = tid - 32;
        const float4* mp = reinterpret_cast<const float4*>(&g_Mef[(b * FD + r) * FD]);
        float a0 = 0.f, a1 = 0.f;
        #pragma unroll
        for (int q = 0; q < 4; q++) {
            float4 mv = __ldg(&mp[q]);
            a0 = fmaf(mv.x, su[32 + 4*q+0], a0);
            a1 = fmaf(mv.y, su[32 + 4*q+1], a1);
            a0 = fmaf(mv.z, su[32 + 4*q+2], a0);
            a1 = fmaf(mv.w, su[32 + 4*q+3], a1);
        }
        acc += a0 + a1;
    } else {
        const int r = tid - 48;
        const float4* mp = reinterpret_cast<const float4*>(&g_Mes[(b * FD + r) * FD]);
        float a0 = 0.f, a1 = 0.f;
        #pragma unroll
        for (int q = 0; q < 4; q++) {
            float4 mv = __ldg(&mp[q]);
            a0 = fmaf(mv.x, su[48 + 4*q+0], a0);
            a1 = fmaf(mv.y, su[48 + 4*q+1], a1);
            a0 = fmaf(mv.z, su[48 + 4*q+2], a0);
            a1 = fmaf(mv.w, su[48 + 4*q+3], a1);
        }
        acc += a0 + a1;
    }
    sc[tid] = acc;
    __syncthreads();

    float o0 = 0.f, o1 = 0.f, o2 = 0.f, o3 = 0.f;
    float o4 = 0.f, o5 = 0.f, o6 = 0.f, o7 = 0.f;
    #pragma unroll
    for (int d = 0; d < 64; d += 8) {
        o0 = fmaf(sc[d+0], sw[(d+0) * 64 + tid], o0);
        o1 = fmaf(sc[d+1], sw[(d+1) * 64 + tid], o1);
        o2 = fmaf(sc[d+2], sw[(d+2) * 64 + tid], o2);
        o3 = fmaf(sc[d+3], sw[(d+3) * 64 + tid], o3);
        o4 = fmaf(sc[d+4], sw[(d+4) * 64 + tid], o4);
        o5 = fmaf(sc[d+5], sw[(d+5) * 64 + tid], o5);
        o6 = fmaf(sc[d+6], sw[(d+6) * 64 + tid], o6);
        o7 = fmaf(sc[d+7], sw[(d+7) * 64 + tid], o7);
    }
    const float osum = ((o0 + o1) + (o2 + o3)) + ((o4 + o5) + (o6 + o7));
    out[b * 64 + tid] = osum + __ldg(&out_b[tid]);
}

// ---------------------------------------------------------------------------
extern "C" void kernel_launch(void* const* d_in, const int* in_sizes, int n_in,
                              void* d_out, int out_size)
{
    const int*   seq    = (const int*)  d_in[0];
    const float* embed  = (const float*)d_in[1];
    const float* w1     = (const float*)d_in[2];
    const float* b1     = (const float*)d_in[3];
    const float* w2     = (const float*)d_in[4];
    const float* b2     = (const float*)d_in[5];
    const float* ln_g   = (const float*)d_in[6];
    const float* ln_b   = (const float*)d_in[7];
    const float* sem_w  = (const float*)d_in[8];
    const float* sem_b  = (const float*)d_in[9];
    const float* fast_w = (const float*)d_in[10];
    const float* fast_b = (const float*)d_in[11];
    const float* slow_w = (const float*)d_in[12];
    const float* slow_b = (const float*)d_in[13];
    const float* out_w  = (const float*)d_in[14];
    const float* out_b  = (const float*)d_in[15];
    float* out = (float*)d_out;

    lut_kernel<<<NVOC, 128>>>(embed, w1, b1, w2, b2, ln_g, ln_b,
                              sem_w, sem_b, fast_w, fast_b, slow_w, slow_b);
    scan_kernel<<<NFWD + NBWD, 128>>>(seq);
    join_kernel<<<NB, 64>>>(out_w, out_b, out);
}